// round 1
// baseline (speedup 1.0000x reference)
#include <cuda_runtime.h>
#include <cstdint>

// NN upsample x2, NHWC fp32: (8,128,128,256) -> (8,256,256,256)
// One thread per input float4: 1x LDG.128, 4x STG.128 (2 in W, 2 in H).
// Read traffic = 134 MB (minimum), write = 537 MB (minimum).

static constexpr int B  = 8;
static constexpr int H  = 128;
static constexpr int W  = 128;
static constexpr int C4 = 256 / 4;   // 64 float4 per pixel
static constexpr int WO = W * 2;     // 256
static constexpr long long N_IN4 = (long long)B * H * W * C4;  // 8,388,608

__global__ __launch_bounds__(256, 8)
void upsample2x_kernel(const float4* __restrict__ in, float4* __restrict__ out)
{
    long long idx = (long long)blockIdx.x * blockDim.x + threadIdx.x;
    if (idx >= N_IN4) return;

    // Decompose: idx = ((b*H + h)*W + w)*C4 + c4
    int c4 = (int)(idx & (C4 - 1));          // C4 = 64, power of 2
    long long t = idx >> 6;                  // (b*H + h)*W + w
    int w = (int)(t & (W - 1));              // W = 128, power of 2
    long long bh = t >> 7;                   // b*H + h  (don't need to split b/h)

    float4 v = in[idx];

    // Output pixel (2h, 2w) base within [B, 2H, 2W, C4]:
    // ((b*2H + 2h)*2W + 2w)*C4 + c4 = bh*4*W*C4*... careful:
    // b*2H + 2h = 2*bh ; row stride = WO*C4
    long long o = ((2ll * bh) * WO + 2ll * w) * C4 + c4;
    long long rowStride = (long long)WO * C4;   // 16384

    out[o]                  = v;  // (2h,   2w)
    out[o + C4]             = v;  // (2h,   2w+1)
    out[o + rowStride]      = v;  // (2h+1, 2w)
    out[o + rowStride + C4] = v;  // (2h+1, 2w+1)
}

extern "C" void kernel_launch(void* const* d_in, const int* in_sizes, int n_in,
                              void* d_out, int out_size)
{
    const float4* in  = (const float4*)d_in[0];
    float4*       out = (float4*)d_out;

    const int threads = 256;
    const long long blocks = (N_IN4 + threads - 1) / threads;  // 32768
    upsample2x_kernel<<<(unsigned)blocks, threads>>>(in, out);
}